// round 2
// baseline (speedup 1.0000x reference)
#include <cuda_runtime.h>
#include <stdint.h>

// Problem shape (fixed by the dataset)
#define BB 16384
#define TT 128

// ---------------------------------------------------------------------------
// JAX threefry2x32 core (exact integer reproduction)
// ---------------------------------------------------------------------------
__host__ __device__ __forceinline__ uint32_t rotl32(uint32_t x, int d) {
    return (x << d) | (x >> (32 - d));
}

__host__ __device__ __forceinline__ void threefry2x32(uint32_t k0, uint32_t k1,
                                                      uint32_t& x0, uint32_t& x1) {
    uint32_t k2 = k0 ^ k1 ^ 0x1BD11BDAu;
    x0 += k0; x1 += k1;
#define TF_R(r) { x0 += x1; x1 = rotl32(x1, (r)); x1 ^= x0; }
    TF_R(13) TF_R(15) TF_R(26) TF_R(6)
    x0 += k1; x1 += k2 + 1u;
    TF_R(17) TF_R(29) TF_R(16) TF_R(24)
    x0 += k2; x1 += k0 + 2u;
    TF_R(13) TF_R(15) TF_R(26) TF_R(6)
    x0 += k0; x1 += k1 + 3u;
    TF_R(17) TF_R(29) TF_R(16) TF_R(24)
    x0 += k1; x1 += k2 + 4u;
    TF_R(13) TF_R(15) TF_R(26) TF_R(6)
    x0 += k2; x1 += k0 + 5u;
#undef TF_R
}

// jax.random.uniform(key,(B,),f32)[b] under jax_threefry_partitionable=True:
//   counters (hi, lo) = (0, b); 32-bit bits = out0 ^ out1
__device__ __forceinline__ float jax_uniform_at(uint32_t ka, uint32_t kb, int b) {
    uint32_t x0 = 0u, x1 = (uint32_t)b;
    threefry2x32(ka, kb, x0, x1);
    uint32_t bits = x0 ^ x1;
    uint32_t f = (bits >> 9) | 0x3F800000u;
    return __uint_as_float(f) - 1.0f;
}

// ---------------------------------------------------------------------------
// Fused kernel: one block per batch row b, one thread per token t
// ---------------------------------------------------------------------------
__global__ __launch_bounds__(TT) void rot_randomizer_kernel(
    const float* __restrict__ pos,   // [B,T,3]
    const float* __restrict__ quat,  // [B,T,4] xyzw
    float* __restrict__ pos_out,     // [B,T,3]
    float* __restrict__ quat_out,    // [B,T,4] xyzw
    float* __restrict__ R_out,       // [B,3,3]
    uint32_t k0a, uint32_t k0b, uint32_t k1a, uint32_t k1b,
    uint32_t k2a, uint32_t k2b, uint32_t k3a, uint32_t k3b)
{
    __shared__ float sU[4];
    __shared__ float sR[9];

    const int b = blockIdx.x;
    const int t = threadIdx.x;

    // --- threads 0..3: the four per-batch uniforms (ax, ay, az, mask) ---
    if (t < 4) {
        uint32_t ka, kb;
        if      (t == 0) { ka = k0a; kb = k0b; }
        else if (t == 1) { ka = k1a; kb = k1b; }
        else if (t == 2) { ka = k2a; kb = k2b; }
        else             { ka = k3a; kb = k3b; }
        sU[t] = jax_uniform_at(ka, kb, b);
    }
    __syncthreads();

    // --- thread 0: build R = (Rz @ Ry) @ Rx, write to smem + Rf output ---
    if (t == 0) {
        const float PI_F = 3.14159265358979323846f;  // rounds to f32 pi
        const bool mask = sU[3] < 0.015625f;          // 1/64
        float ax = mask ? 0.0f : ((sU[0] * 2.0f) * PI_F - PI_F);
        float ay = mask ? 0.0f : ((sU[1] * 2.0f) * PI_F - PI_F);
        float az = mask ? 0.0f : ((sU[2] * 2.0f) * PI_F - PI_F);
        float sx, cx, sy, cy, sz, cz;
        sincosf(ax, &sx, &cx);
        sincosf(ay, &sy, &cy);
        sincosf(az, &sz, &cz);
        float r00 = cz * cy;
        float r01 = (cz * sy) * sx - sz * cx;
        float r02 = (cz * sy) * cx + sz * sx;
        float r10 = sz * cy;
        float r11 = (sz * sy) * sx + cz * cx;
        float r12 = (sz * sy) * cx - cz * sx;
        float r20 = -sy;
        float r21 = cy * sx;
        float r22 = cy * cx;
        sR[0] = r00; sR[1] = r01; sR[2] = r02;
        sR[3] = r10; sR[4] = r11; sR[5] = r12;
        sR[6] = r20; sR[7] = r21; sR[8] = r22;
        float* Ro = R_out + (size_t)b * 9;
        Ro[0] = r00; Ro[1] = r01; Ro[2] = r02;
        Ro[3] = r10; Ro[4] = r11; Ro[5] = r12;
        Ro[6] = r20; Ro[7] = r21; Ro[8] = r22;
    }
    __syncthreads();

    const float r00 = sR[0], r01 = sR[1], r02 = sR[2];
    const float r10 = sR[3], r11 = sR[4], r12 = sR[5];
    const float r20 = sR[6], r21 = sR[7], r22 = sR[8];

    const size_t idx = (size_t)b * TT + t;

    // --- rotate position ---
    const float px = pos[idx * 3 + 0];
    const float py = pos[idx * 3 + 1];
    const float pz = pos[idx * 3 + 2];
    pos_out[idx * 3 + 0] = r00 * px + r01 * py + r02 * pz;
    pos_out[idx * 3 + 1] = r10 * px + r11 * py + r12 * pz;
    pos_out[idx * 3 + 2] = r20 * px + r21 * py + r22 * pz;

    // --- quat (xyzw in memory) -> wxyz -> rotation matrix Q ---
    const float4 q = reinterpret_cast<const float4*>(quat)[idx];
    const float x = q.x, y = q.y, z = q.z, w = q.w;
    const float two = 2.0f / (w * w + x * x + y * y + z * z);
    const float q00 = 1.0f - two * (y * y + z * z);
    const float q01 = two * (x * y - z * w);
    const float q02 = two * (x * z + y * w);
    const float q10 = two * (x * y + z * w);
    const float q11 = 1.0f - two * (x * x + z * z);
    const float q12 = two * (y * z - x * w);
    const float q20 = two * (x * z - y * w);
    const float q21 = two * (y * z + x * w);
    const float q22 = 1.0f - two * (x * x + y * y);

    // --- M = R * Q ---
    const float m00 = r00 * q00 + r01 * q10 + r02 * q20;
    const float m01 = r00 * q01 + r01 * q11 + r02 * q21;
    const float m02 = r00 * q02 + r01 * q12 + r02 * q22;
    const float m10 = r10 * q00 + r11 * q10 + r12 * q20;
    const float m11 = r10 * q01 + r11 * q11 + r12 * q21;
    const float m12 = r10 * q02 + r11 * q12 + r12 * q22;
    const float m20 = r20 * q00 + r21 * q10 + r22 * q20;
    const float m21 = r20 * q01 + r21 * q11 + r22 * q21;
    const float m22 = r20 * q02 + r21 * q12 + r22 * q22;

    // --- mat_to_quat (pytorch3d convention, first-max argmax, clip, 0.1 floor) ---
    float t0 = 1.0f + m00 + m11 + m22;
    float t1 = 1.0f + m00 - m11 - m22;
    float t2 = 1.0f - m00 + m11 - m22;
    float t3 = 1.0f - m00 - m11 + m22;
    t0 = fmaxf(t0, 1e-8f);
    t1 = fmaxf(t1, 1e-8f);
    t2 = fmaxf(t2, 1e-8f);
    t3 = fmaxf(t3, 1e-8f);
    const float qa0 = sqrtf(t0);
    const float qa1 = sqrtf(t1);
    const float qa2 = sqrtf(t2);
    const float qa3 = sqrtf(t3);

    int best = 0; float bv = qa0;
    if (qa1 > bv) { bv = qa1; best = 1; }
    if (qa2 > bv) { bv = qa2; best = 2; }
    if (qa3 > bv) { bv = qa3; best = 3; }

    float cw, cx_, cy_, cz_;
    if (best == 0) {
        cw = qa0 * qa0; cx_ = m21 - m12; cy_ = m02 - m20; cz_ = m10 - m01;
    } else if (best == 1) {
        cw = m21 - m12; cx_ = qa1 * qa1; cy_ = m01 + m10; cz_ = m02 + m20;
    } else if (best == 2) {
        cw = m02 - m20; cx_ = m10 + m01; cy_ = qa2 * qa2; cz_ = m12 + m21;
    } else {
        cw = m10 - m01; cx_ = m20 + m02; cy_ = m21 + m12; cz_ = qa3 * qa3;
    }
    const float denom = 2.0f * fmaxf(bv, 0.1f);

    float4 qo;
    qo.x = cx_ / denom;  // x
    qo.y = cy_ / denom;  // y
    qo.z = cz_ / denom;  // z
    qo.w = cw  / denom;  // w   (output order xyzw)
    reinterpret_cast<float4*>(quat_out)[idx] = qo;
}

// ---------------------------------------------------------------------------
// Host: derive the four _build_R keys from seed 42 (partitionable threefry)
// ---------------------------------------------------------------------------
static void host_threefry(uint32_t k0, uint32_t k1, uint32_t x0, uint32_t x1,
                          uint32_t* o0, uint32_t* o1) {
    threefry2x32(k0, k1, x0, x1);
    *o0 = x0; *o1 = x1;
}

extern "C" void kernel_launch(void* const* d_in, const int* in_sizes, int n_in,
                              void* d_out, int out_size) {
    const float* pos  = (const float*)d_in[0];
    const float* quat = (const float*)d_in[1];
    float* out = (float*)d_out;

    // jax_threefry_partitionable=True scheme:
    // key = jax.random.key(42) -> data (0, 42)
    // key, sub = split(key): child i = full output pair of threefry(key; 0, i)
    uint32_t sa, sb;
    host_threefry(0u, 42u, 0u, 1u, &sa, &sb);   // sub = child 1

    // k = split(sub, 4): k[j] = full output pair of threefry(sub; 0, j)
    uint32_t kj[4][2];
    for (uint32_t j = 0; j < 4; j++) {
        host_threefry(sa, sb, 0u, j, &kj[j][0], &kj[j][1]);
    }

    float* pos_out  = out;
    float* quat_out = out + (size_t)BB * TT * 3;
    float* R_out    = out + (size_t)BB * TT * 7;

    rot_randomizer_kernel<<<BB, TT>>>(
        pos, quat, pos_out, quat_out, R_out,
        kj[0][0], kj[0][1],
        kj[1][0], kj[1][1],
        kj[2][0], kj[2][1],
        kj[3][0], kj[3][1]);
}

// round 3
// speedup vs baseline: 1.1454x; 1.1454x over previous
#include <cuda_runtime.h>
#include <stdint.h>

#define BB 16384
#define TT 128

// ---------------------------------------------------------------------------
// JAX threefry2x32 (exact integer reproduction, partitionable scheme)
// ---------------------------------------------------------------------------
__host__ __device__ __forceinline__ uint32_t rotl32(uint32_t x, int d) {
    return (x << d) | (x >> (32 - d));
}

__host__ __device__ __forceinline__ void threefry2x32(uint32_t k0, uint32_t k1,
                                                      uint32_t& x0, uint32_t& x1) {
    uint32_t k2 = k0 ^ k1 ^ 0x1BD11BDAu;
    x0 += k0; x1 += k1;
#define TF_R(r) { x0 += x1; x1 = rotl32(x1, (r)); x1 ^= x0; }
    TF_R(13) TF_R(15) TF_R(26) TF_R(6)
    x0 += k1; x1 += k2 + 1u;
    TF_R(17) TF_R(29) TF_R(16) TF_R(24)
    x0 += k2; x1 += k0 + 2u;
    TF_R(13) TF_R(15) TF_R(26) TF_R(6)
    x0 += k0; x1 += k1 + 3u;
    TF_R(17) TF_R(29) TF_R(16) TF_R(24)
    x0 += k1; x1 += k2 + 4u;
    TF_R(13) TF_R(15) TF_R(26) TF_R(6)
    x0 += k2; x1 += k0 + 5u;
#undef TF_R
}

// jax.random.uniform(key,(B,),f32)[b] under jax_threefry_partitionable=True
__device__ __forceinline__ float jax_uniform_at(uint32_t ka, uint32_t kb, int b) {
    uint32_t x0 = 0u, x1 = (uint32_t)b;
    threefry2x32(ka, kb, x0, x1);
    uint32_t bits = x0 ^ x1;
    uint32_t f = (bits >> 9) | 0x3F800000u;
    return __uint_as_float(f) - 1.0f;
}

// ---------------------------------------------------------------------------
// One warp per batch row; each lane handles 4 tokens with float4 I/O.
// Block = 128 threads = 4 rows; grid = BB/4.
// ---------------------------------------------------------------------------
__global__ __launch_bounds__(128) void rot_randomizer_kernel(
    const float* __restrict__ pos,   // [B,T,3]
    const float* __restrict__ quat,  // [B,T,4] xyzw
    float* __restrict__ pos_out,     // [B,T,3]
    float* __restrict__ quat_out,    // [B,T,4] xyzw
    float* __restrict__ R_out,       // [B,3,3]
    uint32_t k0a, uint32_t k0b, uint32_t k1a, uint32_t k1b,
    uint32_t k2a, uint32_t k2b, uint32_t k3a, uint32_t k3b)
{
    const int warp = threadIdx.x >> 5;
    const int lane = threadIdx.x & 31;
    const int b = blockIdx.x * 4 + warp;
    const unsigned FULL = 0xFFFFFFFFu;

    // --- lanes 0..3: the four per-row uniforms (ax, ay, az, mask) ---
    float u = 0.0f;
    if (lane < 4) {
        uint32_t ka = (lane == 0) ? k0a : (lane == 1) ? k1a : (lane == 2) ? k2a : k3a;
        uint32_t kb = (lane == 0) ? k0b : (lane == 1) ? k1b : (lane == 2) ? k2b : k3b;
        u = jax_uniform_at(ka, kb, b);
    }
    const float u0 = __shfl_sync(FULL, u, 0);
    const float u1 = __shfl_sync(FULL, u, 1);
    const float u2 = __shfl_sync(FULL, u, 2);
    const float u3 = __shfl_sync(FULL, u, 3);

    const float PI_F = 3.14159265358979323846f;
    const bool mask = u3 < 0.015625f;  // 1/64
    const float ax = mask ? 0.0f : ((u0 * 2.0f) * PI_F - PI_F);
    const float ay = mask ? 0.0f : ((u1 * 2.0f) * PI_F - PI_F);
    const float az = mask ? 0.0f : ((u2 * 2.0f) * PI_F - PI_F);

    // --- distribute 6 sincos evals across lanes 0..5, then broadcast ---
    float amine = 0.0f;
    if      (lane == 0) amine = ax;
    else if (lane == 1) amine = ay;
    else if (lane == 2) amine = az;
    else if (lane == 3) amine = 0.5f * ax;
    else if (lane == 4) amine = 0.5f * ay;
    else if (lane == 5) amine = 0.5f * az;
    float s_, c_;
    sincosf(amine, &s_, &c_);
    const float sx  = __shfl_sync(FULL, s_, 0), cx  = __shfl_sync(FULL, c_, 0);
    const float sy  = __shfl_sync(FULL, s_, 1), cy  = __shfl_sync(FULL, c_, 1);
    const float sz  = __shfl_sync(FULL, s_, 2), cz  = __shfl_sync(FULL, c_, 2);
    const float sx2 = __shfl_sync(FULL, s_, 3), cx2 = __shfl_sync(FULL, c_, 3);
    const float sy2 = __shfl_sync(FULL, s_, 4), cy2 = __shfl_sync(FULL, c_, 4);
    const float sz2 = __shfl_sync(FULL, s_, 5), cz2 = __shfl_sync(FULL, c_, 5);

    // --- R = (Rz @ Ry) @ Rx — same expressions as the passing R2 kernel ---
    const float r00 = cz * cy;
    const float r01 = (cz * sy) * sx - sz * cx;
    const float r02 = (cz * sy) * cx + sz * sx;
    const float r10 = sz * cy;
    const float r11 = (sz * sy) * sx + cz * cx;
    const float r12 = (sz * sy) * cx - cz * sx;
    const float r20 = -sy;
    const float r21 = cy * sx;
    const float r22 = cy * cx;

    if (lane == 0) {
        float* Ro = R_out + b * 9;
        Ro[0] = r00; Ro[1] = r01; Ro[2] = r02;
        Ro[3] = r10; Ro[4] = r11; Ro[5] = r12;
        Ro[6] = r20; Ro[7] = r21; Ro[8] = r22;
    }

    // --- r_q = quat(Rz) (x) quat(Ry) (x) quat(Rx), wxyz ---
    const float w1 = cy2 * cx2;
    const float x1q = cy2 * sx2;
    const float y1q = cx2 * sy2;
    const float z1q = -sy2 * sx2;
    const float rw = cz2 * w1  - sz2 * z1q;
    const float rx = cz2 * x1q - sz2 * y1q;
    const float ry = cz2 * y1q + sz2 * x1q;
    const float rz = cz2 * z1q + sz2 * w1;

    // ------------------- 4 tokens per lane, float4 I/O -------------------
    // positions: 4 tokens = 12 floats = 3 aligned float4
    {
        const int off = b * (TT * 3) + lane * 12;
        const float4 A = *reinterpret_cast<const float4*>(pos + off);
        const float4 Bv = *reinterpret_cast<const float4*>(pos + off + 4);
        const float4 C = *reinterpret_cast<const float4*>(pos + off + 8);

        // p0..p3
        const float p0x = A.x,  p0y = A.y,  p0z = A.z;
        const float p1x = A.w,  p1y = Bv.x, p1z = Bv.y;
        const float p2x = Bv.z, p2y = Bv.w, p2z = C.x;
        const float p3x = C.y,  p3y = C.z,  p3z = C.w;

        const float o0x = r00 * p0x + r01 * p0y + r02 * p0z;
        const float o0y = r10 * p0x + r11 * p0y + r12 * p0z;
        const float o0z = r20 * p0x + r21 * p0y + r22 * p0z;
        const float o1x = r00 * p1x + r01 * p1y + r02 * p1z;
        const float o1y = r10 * p1x + r11 * p1y + r12 * p1z;
        const float o1z = r20 * p1x + r21 * p1y + r22 * p1z;
        const float o2x = r00 * p2x + r01 * p2y + r02 * p2z;
        const float o2y = r10 * p2x + r11 * p2y + r12 * p2z;
        const float o2z = r20 * p2x + r21 * p2y + r22 * p2z;
        const float o3x = r00 * p3x + r01 * p3y + r02 * p3z;
        const float o3y = r10 * p3x + r11 * p3y + r12 * p3z;
        const float o3z = r20 * p3x + r21 * p3y + r22 * p3z;

        float4 D, E, F;
        D.x = o0x; D.y = o0y; D.z = o0z; D.w = o1x;
        E.x = o1y; E.y = o1z; E.z = o2x; E.w = o2y;
        F.x = o2z; F.y = o3x; F.z = o3y; F.w = o3z;
        *reinterpret_cast<float4*>(pos_out + off)     = D;
        *reinterpret_cast<float4*>(pos_out + off + 4) = E;
        *reinterpret_cast<float4*>(pos_out + off + 8) = F;
    }

    // quats: 4 tokens = 4 aligned float4
    {
        const int qoff = b * (TT * 4) + lane * 16;
        const float4* qi = reinterpret_cast<const float4*>(quat + qoff);
        float4*       qo = reinterpret_cast<float4*>(quat_out + qoff);

#pragma unroll
        for (int j = 0; j < 4; j++) {
            const float4 q = qi[j];
            const float qx = q.x, qy = q.y, qz = q.z, qw = q.w;  // xyzw in memory

            // p = r_q (x) q   (wxyz)
            const float pw = rw * qw - rx * qx - ry * qy - rz * qz;
            const float px = rw * qx + rx * qw + ry * qz - rz * qy;
            const float py = rw * qy - rx * qz + ry * qw + rz * qx;
            const float pz = rw * qz + rx * qy - ry * qx + rz * qw;

            // argmax over |pw|,|px|,|py|,|pz| (first-max), sign-canonicalize
            const float aw = fabsf(pw), axv = fabsf(px),
                        ayv = fabsf(py), azv = fabsf(pz);
            float bv = aw, bs = pw;
            if (axv > bv) { bv = axv; bs = px; }
            if (ayv > bv) { bv = ayv; bs = py; }
            if (azv > bv) { bv = azv; bs = pz; }

            const float n2 = qx * qx + qy * qy + qz * qz + qw * qw;
            float f = rsqrtf(n2);
            f = (bs < 0.0f) ? -f : f;

            float4 o;
            o.x = px * f; o.y = py * f; o.z = pz * f; o.w = pw * f;  // xyzw
            qo[j] = o;
        }
    }
}

// ---------------------------------------------------------------------------
// Host: derive the four _build_R keys from seed 42 (partitionable threefry)
// ---------------------------------------------------------------------------
static void host_threefry(uint32_t k0, uint32_t k1, uint32_t x0, uint32_t x1,
                          uint32_t* o0, uint32_t* o1) {
    threefry2x32(k0, k1, x0, x1);
    *o0 = x0; *o1 = x1;
}

extern "C" void kernel_launch(void* const* d_in, const int* in_sizes, int n_in,
                              void* d_out, int out_size) {
    const float* pos  = (const float*)d_in[0];
    const float* quat = (const float*)d_in[1];
    float* out = (float*)d_out;

    // key = jax.random.key(42) -> (0, 42); sub = split(key)[1]
    uint32_t sa, sb;
    host_threefry(0u, 42u, 0u, 1u, &sa, &sb);

    // k = split(sub, 4): k[j] = full output pair of threefry(sub; 0, j)
    uint32_t kj[4][2];
    for (uint32_t j = 0; j < 4; j++) {
        host_threefry(sa, sb, 0u, j, &kj[j][0], &kj[j][1]);
    }

    float* pos_out  = out;
    float* quat_out = out + (size_t)BB * TT * 3;
    float* R_out    = out + (size_t)BB * TT * 7;

    rot_randomizer_kernel<<<BB / 4, 128>>>(
        pos, quat, pos_out, quat_out, R_out,
        kj[0][0], kj[0][1],
        kj[1][0], kj[1][1],
        kj[2][0], kj[2][1],
        kj[3][0], kj[3][1]);
}